// round 14
// baseline (speedup 1.0000x reference)
#include <cuda_runtime.h>
#include <math.h>

typedef unsigned long long u64;
typedef unsigned int u32;

#define SPLITK 4

// Split-K partial sums of x @ W^T (bias added in circuit kernel). No allocs.
__device__ float g_com4[SPLITK][1024 * 512];

// ---------------------------------------------------------------------------
// Packed fp32x2 helpers (PTX-only)
// ---------------------------------------------------------------------------
__device__ __forceinline__ u64 pk2(float lo, float hi) {
    u64 d; asm("mov.b64 %0, {%1, %2};" : "=l"(d) : "f"(lo), "f"(hi)); return d;
}
__device__ __forceinline__ u64 fma2(u64 a, u64 b, u64 c) {
    u64 d; asm("fma.rn.f32x2 %0, %1, %2, %3;" : "=l"(d) : "l"(a), "l"(b), "l"(c)); return d;
}
__device__ __forceinline__ u64 mul2(u64 a, u64 b) {
    u64 d; asm("mul.rn.f32x2 %0, %1, %2;" : "=l"(d) : "l"(a), "l"(b)); return d;
}
__device__ __forceinline__ u64 add2(u64 a, u64 b) {
    u64 d; asm("add.rn.f32x2 %0, %1, %2;" : "=l"(d) : "l"(a), "l"(b)); return d;
}
__device__ __forceinline__ void unpk2(float& lo, float& hi, u64 d) {
    asm("mov.b64 {%0, %1}, %2;" : "=f"(lo), "=f"(hi) : "l"(d));
}
// swap halves: (x, y) -> (y, x)
__device__ __forceinline__ u64 hswap(u64 a) {
    float lo, hi; unpk2(lo, hi, a);
    return pk2(hi, lo);
}

__device__ __forceinline__ void cp_async16(u32 smem_addr, const void* gptr) {
    asm volatile("cp.async.cg.shared.global [%0], [%1], 16;"
                 :: "r"(smem_addr), "l"(gptr) : "memory");
}
__device__ __forceinline__ void cp_commit() {
    asm volatile("cp.async.commit_group;" ::: "memory");
}
__device__ __forceinline__ void cp_wait2() {
    asm volatile("cp.async.wait_group 2;" ::: "memory");
}

// ---------------------------------------------------------------------------
// GEMM-TC v5: split-K partials of x @ W^T via mma.sync m16n8k8 tf32.
// CTA tile 128x128, BK=16, 256 threads = 8 warps (2m x 4n of 64x32 tiles).
// grid (4, 8, 4) = 128 CTAs -> single wave.  K/CTA = 512 -> 32 iters.
// 4-stage cp.async pipeline (64 KB dynamic smem ring), wait_group 2:
// loads get ~3 iterations to land -> DRAM latency fully hidden.
// Smem k4-packed: elem(q, row, c) at q*512 + row*4 + c  (q = k>>2, c = k&3).
// Frag LDS banks (4*mr + kc) mod 32 all-distinct -> conflict-free.
// No explicit tf32 cvt: raw f32 bits fed to MMA (hw truncates mantissa).
// ---------------------------------------------------------------------------
__global__ __launch_bounds__(256)
void gemm_tc5(const float* __restrict__ A, const float* __restrict__ Wm)
{
    extern __shared__ __align__(16) float smem[];
    float* sA = smem;               // [4][2048] : stage, q*512 + row*4 + c
    float* sW = smem + 4 * 2048;    // [4][2048]

    const int t  = threadIdx.x;
    const int n0 = blockIdx.x * 128;
    const int m0 = blockIdx.y * 128;
    const int kb = blockIdx.z * 512;

    // loader mapping: thread t -> row r = t>>1, q-pair qb = (t&1)*2
    const int r  = t >> 1;
    const int qb = (t & 1) << 1;
    const float* Ap = A  + (size_t)(m0 + r) * 2048 + kb + qb * 4;
    const float* Wp = Wm + (size_t)(n0 + r) * 2048 + kb + qb * 4;
    const u32 sAbase = (u32)__cvta_generic_to_shared(sA) + (qb * 512 + r * 4) * 4;
    const u32 sWbase = (u32)__cvta_generic_to_shared(sW) + (qb * 512 + r * 4) * 4;

    // mma mapping
    const int lane = t & 31;
    const int wid  = t >> 5;
    const int wm   = wid >> 2;         // 0..1  (m half, 64 rows)
    const int wn   = wid & 3;          // 0..3  (n quarter, 32 cols)
    const int mr   = lane >> 2;        // 0..7
    const int kc   = lane & 3;         // 0..3

    float acc[4][4][4];
    #pragma unroll
    for (int mt = 0; mt < 4; ++mt)
        #pragma unroll
        for (int nt = 0; nt < 4; ++nt)
            #pragma unroll
            for (int i = 0; i < 4; ++i) acc[mt][nt][i] = 0.f;

    // prologue: issue stages 0..2 (one commit group each)
    #pragma unroll
    for (int s = 0; s < 3; ++s) {
        u32 da = sAbase + (s & 3) * 2048 * 4;
        u32 dw = sWbase + (s & 3) * 2048 * 4;
        cp_async16(da,       Ap + s * 16);
        cp_async16(da + 2048, Ap + s * 16 + 4);   // q+1 block: +512 floats
        cp_async16(dw,       Wp + s * 16);
        cp_async16(dw + 2048, Wp + s * 16 + 4);
        cp_commit();
    }

    const u32 sAu = (u32)__cvta_generic_to_shared(sA);
    const u32 sWu = (u32)__cvta_generic_to_shared(sW);
    (void)sAu; (void)sWu;

    #pragma unroll 1
    for (int it = 0; it < 32; ++it) {
        cp_wait2();              // oldest pending group (stage it) complete
        __syncthreads();

        // issue stage it+3 into buffer (it+3)%4 (freed: compute(it-1) done)
        if (it + 3 < 32) {
            u32 da = sAbase + ((it + 3) & 3) * 2048 * 4;
            u32 dw = sWbase + ((it + 3) & 3) * 2048 * 4;
            cp_async16(da,       Ap + (it + 3) * 16);
            cp_async16(da + 2048, Ap + (it + 3) * 16 + 4);
            cp_async16(dw,       Wp + (it + 3) * 16);
            cp_async16(dw + 2048, Wp + (it + 3) * 16 + 4);
        }
        cp_commit();             // commit (possibly empty) to keep group count

        const u32* bufA = (const u32*)(sA + (it & 3) * 2048);
        const u32* bufW = (const u32*)(sW + (it & 3) * 2048);

        #pragma unroll
        for (int ks = 0; ks < 16; ks += 8) {
            const int q0 = ks >> 2;          // 0 or 2
            u32 af[4][4];
            #pragma unroll
            for (int mt = 0; mt < 4; ++mt) {
                int m = wm * 64 + mt * 16 + mr;
                af[mt][0] = bufA[ q0      * 512 + m * 4 + kc];
                af[mt][1] = bufA[ q0      * 512 + (m + 8) * 4 + kc];
                af[mt][2] = bufA[(q0 + 1) * 512 + m * 4 + kc];
                af[mt][3] = bufA[(q0 + 1) * 512 + (m + 8) * 4 + kc];
            }
            u32 bf[4][2];
            #pragma unroll
            for (int nt = 0; nt < 4; ++nt) {
                int n = wn * 32 + nt * 8 + mr;
                bf[nt][0] = bufW[ q0      * 512 + n * 4 + kc];
                bf[nt][1] = bufW[(q0 + 1) * 512 + n * 4 + kc];
            }
            #pragma unroll
            for (int mt = 0; mt < 4; ++mt)
                #pragma unroll
                for (int nt = 0; nt < 4; ++nt) {
                    asm volatile(
                        "mma.sync.aligned.m16n8k8.row.col.f32.tf32.tf32.f32 "
                        "{%0,%1,%2,%3}, {%4,%5,%6,%7}, {%8,%9}, {%0,%1,%2,%3};"
                        : "+f"(acc[mt][nt][0]), "+f"(acc[mt][nt][1]),
                          "+f"(acc[mt][nt][2]), "+f"(acc[mt][nt][3])
                        : "r"(af[mt][0]), "r"(af[mt][1]),
                          "r"(af[mt][2]), "r"(af[mt][3]),
                          "r"(bf[nt][0]), "r"(bf[nt][1]));
                }
        }
    }

    float* Cp = g_com4[blockIdx.z];
    #pragma unroll
    for (int mt = 0; mt < 4; ++mt) {
        #pragma unroll
        for (int nt = 0; nt < 4; ++nt) {
            int row = m0 + wm * 64 + mt * 16 + mr;
            int col = n0 + wn * 32 + nt * 8 + 2 * kc;
            *(float2*)&Cp[(size_t)row * 512 + col] =
                make_float2(acc[mt][nt][0], acc[mt][nt][1]);
            *(float2*)&Cp[(size_t)(row + 8) * 512 + col] =
                make_float2(acc[mt][nt][2], acc[mt][nt][3]);
        }
    }
}

// ---------------------------------------------------------------------------
// Quantum circuit (R5-proven, ~51us, FROZEN): 1 CTA per batch row, state
// (4096 complex, AoS u64) in SMEM.  Wire w <-> bit (11 - w).
// Swizzle a(i) = i ^ ((i>>4) & 0xF).
// ---------------------------------------------------------------------------
__device__ __forceinline__ int swz(int i) { return i ^ ((i >> 4) & 0xF); }

// Packed complex 2x2 gate on pairs over local bit LB.
// c[8] splats: c[2e] = (m.x, m.x), c[2e+1] = (-m.y, m.y)  (negation folded).
template<int LB>
__device__ __forceinline__ void rot2(u64* v, const u64* __restrict__ cf)
{
    u64 c0 = cf[0], c1 = cf[1], c2 = cf[2], c3 = cf[3];
    u64 c4 = cf[4], c5 = cf[5], c6 = cf[6], c7 = cf[7];
    #pragma unroll
    for (int p = 0; p < 8; ++p) {
        int k0 = ((p >> LB) << (LB + 1)) | (p & ((1 << LB) - 1));
        int k1 = k0 | (1 << LB);
        u64 A = v[k0], B = v[k1];
        u64 As_ = hswap(A), Bs = hswap(B);
        v[k0] = fma2(c0, A, fma2(c1, As_, fma2(c2, B, mul2(c3, Bs))));
        v[k1] = fma2(c4, A, fma2(c5, As_, fma2(c6, B, mul2(c7, Bs))));
    }
}

// Unscaled Hadamard butterfly (scale folded into final reduction).
template<int LB>
__device__ __forceinline__ void h2(u64* v, u64 neg1)
{
    #pragma unroll
    for (int p = 0; p < 8; ++p) {
        int k0 = ((p >> LB) << (LB + 1)) | (p & ((1 << LB) - 1));
        int k1 = k0 | (1 << LB);
        u64 A = v[k0], B = v[k1];
        v[k0] = add2(A, B);
        v[k1] = fma2(neg1, B, A);
    }
}

// Net gather index of the 12-CNOT chain with range R (GF(2)-linear).
template<int R>
__device__ __forceinline__ int cnotG(int i)
{
    #pragma unroll
    for (int w = 11; w >= 0; --w) {
        int pc = 11 - w;
        int pt = 11 - ((w + R) % 12);
        i ^= ((i >> pc) & 1) << pt;
    }
    return i;
}

__global__ __launch_bounds__(256, 2)
void circuit_kernel(const float* __restrict__ x,    // (1024, 2048) img angles
                    const float* __restrict__ bias, // (512,)
                    const float* __restrict__ qp,   // (2, 12, 3)
                    float* __restrict__ out)        // (1024,)
{
    __shared__ u64 st[4096];             // 32 KB state (packed complex)
    __shared__ u64 cf2[2][12][8];        // splatted gate coefficients
    __shared__ float red[8];

    const int t = threadIdx.x;
    const int b = blockIdx.x;
    const float* img = x + (size_t)b * 2048;
    const size_t crow = (size_t)b * 512;

    // --- Rot matrices, splatted: Rot = RZ(omega) RY(theta) RZ(phi) ---
    if (t < 24) {
        int l = t / 12, w = t % 12;
        float phi = qp[(l * 12 + w) * 3 + 0];
        float th  = qp[(l * 12 + w) * 3 + 1];
        float om  = qp[(l * 12 + w) * 3 + 2];
        float sh, ch;  sincosf(0.5f * th, &sh, &ch);
        float sa, ca;  sincosf(0.5f * (phi + om), &sa, &ca);
        float sb, cb;  sincosf(0.5f * (phi - om), &sb, &cb);
        u64* c = cf2[l][w];
        c[0] = pk2( ch * ca,  ch * ca);
        c[1] = pk2( ch * sa, -ch * sa);
        c[2] = pk2(-sh * cb, -sh * cb);
        c[3] = pk2( sh * sb, -sh * sb);
        c[4] = pk2( sh * cb,  sh * cb);
        c[5] = pk2( sh * sb, -sh * sb);
        c[6] = pk2( ch * ca,  ch * ca);
        c[7] = pk2(-ch * sa,  ch * sa);
    }
    __syncthreads();

    const u64 neg1 = pk2(-1.f, -1.f);
    u64 v[16];

    // ===== Pass 1 (A: bits 0-3 local) : analytic FRQI(com), L0 Rots 11..8
    #pragma unroll
    for (int k = 0; k < 16; ++k) {
        int i = (t << 4) | k;
        if (i & 3) {
            v[k] = 0ull;
        } else {
            int j = (i >> 2) & 511;
            int aidx = __brev((unsigned)j) >> 23;
            float comv = bias[aidx];
            #pragma unroll
            for (int s = 0; s < SPLITK; ++s) comv += g_com4[s][crow + aidx];
            float sn, cs; __sincosf(0.5f * comv, &sn, &cs);
            float amp = ((i >> 11) & 1) ? sn : cs;
            v[k] = pk2(amp * 0.04419417382415922f, 0.f);  // 1/sqrt(512)
        }
    }
    rot2<0>(v, cf2[0][11]); rot2<1>(v, cf2[0][10]);
    rot2<2>(v, cf2[0][9]);  rot2<3>(v, cf2[0][8]);
    #pragma unroll
    for (int k = 0; k < 16; ++k) st[swz((t << 4) | k)] = v[k];
    __syncthreads();

    // ===== Pass 2 (B: bits 4-7) : L0 Rots 7..4
    #pragma unroll
    for (int k = 0; k < 16; ++k) v[k] = st[swz(((t >> 4) << 8) | (k << 4) | (t & 15))];
    rot2<0>(v, cf2[0][7]); rot2<1>(v, cf2[0][6]);
    rot2<2>(v, cf2[0][5]); rot2<3>(v, cf2[0][4]);
    #pragma unroll
    for (int k = 0; k < 16; ++k) st[swz(((t >> 4) << 8) | (k << 4) | (t & 15))] = v[k];
    __syncthreads();

    // ===== Pass 3 (C: bits 8-11) : L0 Rots 3..0
    #pragma unroll
    for (int k = 0; k < 16; ++k) v[k] = st[swz((k << 8) | t)];
    rot2<0>(v, cf2[0][3]); rot2<1>(v, cf2[0][2]);
    rot2<2>(v, cf2[0][1]); rot2<3>(v, cf2[0][0]);
    #pragma unroll
    for (int k = 0; k < 16; ++k) st[swz((k << 8) | t)] = v[k];
    __syncthreads();

    // ===== Pass 4 (A) : CNOT r=1 folded gather, L1 Rots 11..8
    {
        int base = cnotG<1>(t << 4);
        int m0 = cnotG<1>(1), m1 = cnotG<1>(2), m2 = cnotG<1>(4), m3 = cnotG<1>(8);
        #pragma unroll
        for (int k = 0; k < 16; ++k) {
            int gi = base ^ ((k & 1) ? m0 : 0) ^ ((k & 2) ? m1 : 0)
                          ^ ((k & 4) ? m2 : 0) ^ ((k & 8) ? m3 : 0);
            v[k] = st[swz(gi)];
        }
    }
    __syncthreads();
    rot2<0>(v, cf2[1][11]); rot2<1>(v, cf2[1][10]);
    rot2<2>(v, cf2[1][9]);  rot2<3>(v, cf2[1][8]);
    #pragma unroll
    for (int k = 0; k < 16; ++k) st[swz((t << 4) | k)] = v[k];
    __syncthreads();

    // ===== Pass 5 (B) : L1 Rots 7..4
    #pragma unroll
    for (int k = 0; k < 16; ++k) v[k] = st[swz(((t >> 4) << 8) | (k << 4) | (t & 15))];
    rot2<0>(v, cf2[1][7]); rot2<1>(v, cf2[1][6]);
    rot2<2>(v, cf2[1][5]); rot2<3>(v, cf2[1][4]);
    #pragma unroll
    for (int k = 0; k < 16; ++k) st[swz(((t >> 4) << 8) | (k << 4) | (t & 15))] = v[k];
    __syncthreads();

    // ===== Pass 6 (C) : L1 Rots 3..0
    #pragma unroll
    for (int k = 0; k < 16; ++k) v[k] = st[swz((k << 8) | t)];
    rot2<0>(v, cf2[1][3]); rot2<1>(v, cf2[1][2]);
    rot2<2>(v, cf2[1][1]); rot2<3>(v, cf2[1][0]);
    #pragma unroll
    for (int k = 0; k < 16; ++k) st[swz((k << 8) | t)] = v[k];
    __syncthreads();

    // ===== Pass 7 (A) : CNOT r=2 folded gather, H bits 0-3 (unscaled)
    {
        int base = cnotG<2>(t << 4);
        int m0 = cnotG<2>(1), m1 = cnotG<2>(2), m2 = cnotG<2>(4), m3 = cnotG<2>(8);
        #pragma unroll
        for (int k = 0; k < 16; ++k) {
            int gi = base ^ ((k & 1) ? m0 : 0) ^ ((k & 2) ? m1 : 0)
                          ^ ((k & 4) ? m2 : 0) ^ ((k & 8) ? m3 : 0);
            v[k] = st[swz(gi)];
        }
    }
    __syncthreads();
    h2<0>(v, neg1); h2<1>(v, neg1); h2<2>(v, neg1); h2<3>(v, neg1);
    #pragma unroll
    for (int k = 0; k < 16; ++k) st[swz((t << 4) | k)] = v[k];
    __syncthreads();

    // ===== Pass 8 (B) : H bits 4-7 (unscaled)
    #pragma unroll
    for (int k = 0; k < 16; ++k) v[k] = st[swz(((t >> 4) << 8) | (k << 4) | (t & 15))];
    h2<0>(v, neg1); h2<1>(v, neg1); h2<2>(v, neg1); h2<3>(v, neg1);
    #pragma unroll
    for (int k = 0; k < 16; ++k) st[swz(((t >> 4) << 8) | (k << 4) | (t & 15))] = v[k];
    __syncthreads();

    // ===== Pass 9 (C) : H bits 8-10 (unscaled), UC-RY(img) on wire 0, measure
    #pragma unroll
    for (int k = 0; k < 16; ++k) v[k] = st[swz((k << 8) | t)];
    h2<0>(v, neg1); h2<1>(v, neg1); h2<2>(v, neg1);

    #pragma unroll
    for (int k0 = 0; k0 < 8; ++k0) {
        int i0 = (k0 << 8) | t;
        int aidx = __brev((unsigned)i0) >> 21;
        float sn, cs; __sincosf(0.5f * img[aidx], &sn, &cs);
        u64 A = v[k0], B = v[k0 + 8];
        u64 cs2 = pk2(cs, cs), sn2 = pk2(sn, sn), sn2n = pk2(-sn, -sn);
        v[k0]     = fma2(cs2, A, mul2(sn2n, B));
        v[k0 + 8] = fma2(sn2, A, mul2(cs2, B));
    }

    u64 accN = 0ull, accP = 0ull;
    #pragma unroll
    for (int k = 0; k < 8; ++k)  accN = fma2(v[k], v[k], accN);
    #pragma unroll
    for (int k = 8; k < 16; ++k) accP = fma2(v[k], v[k], accP);
    float pl, ph, nl, nh;
    unpk2(pl, ph, accP); unpk2(nl, nh, accN);
    float acc = (pl + ph) - (nl + nh);

    #pragma unroll
    for (int o = 16; o; o >>= 1) acc += __shfl_xor_sync(0xffffffffu, acc, o);
    if ((t & 31) == 0) red[t >> 5] = acc;
    __syncthreads();
    if (t == 0) {
        float s = 0.f;
        #pragma unroll
        for (int w = 0; w < 8; ++w) s += red[w];
        out[b] = s * (1.0f / 2048.0f);   // fold (1/sqrt(2))^11 (squared) scale
    }
}

// ---------------------------------------------------------------------------
extern "C" void kernel_launch(void* const* d_in, const int* in_sizes, int n_in,
                              void* d_out, int out_size)
{
    const float* x  = (const float*)d_in[0];   // (1024, 2, 32, 32) -> (1024, 2048)
    const float* Wm = (const float*)d_in[1];   // (512, 2048)
    const float* bb = (const float*)d_in[2];   // (512,)
    const float* qp = (const float*)d_in[3];   // (2, 12, 3)
    float* out = (float*)d_out;                // (1024,)

    cudaFuncSetAttribute(gemm_tc5,
                         cudaFuncAttributeMaxDynamicSharedMemorySize, 65536);

    dim3 gemm_grid(512 / 128, 1024 / 128, SPLITK);   // (4, 8, 4) = 128 CTAs
    gemm_tc5<<<gemm_grid, 256, 65536>>>(x, Wm);
    circuit_kernel<<<1024, 256>>>(x, bb, qp, out);
}

// round 15
// speedup vs baseline: 1.0255x; 1.0255x over previous
#include <cuda_runtime.h>
#include <math.h>

typedef unsigned long long u64;
typedef unsigned int u32;

#define SPLITK 8

// Split-K partial sums of x @ W^T (bias added in circuit kernel). No allocs.
__device__ float g_com4[SPLITK][1024 * 512];

// ---------------------------------------------------------------------------
// Packed fp32x2 helpers (PTX-only)
// ---------------------------------------------------------------------------
__device__ __forceinline__ u64 pk2(float lo, float hi) {
    u64 d; asm("mov.b64 %0, {%1, %2};" : "=l"(d) : "f"(lo), "f"(hi)); return d;
}
__device__ __forceinline__ u64 fma2(u64 a, u64 b, u64 c) {
    u64 d; asm("fma.rn.f32x2 %0, %1, %2, %3;" : "=l"(d) : "l"(a), "l"(b), "l"(c)); return d;
}
__device__ __forceinline__ u64 mul2(u64 a, u64 b) {
    u64 d; asm("mul.rn.f32x2 %0, %1, %2;" : "=l"(d) : "l"(a), "l"(b)); return d;
}
__device__ __forceinline__ u64 add2(u64 a, u64 b) {
    u64 d; asm("add.rn.f32x2 %0, %1, %2;" : "=l"(d) : "l"(a), "l"(b)); return d;
}
__device__ __forceinline__ void unpk2(float& lo, float& hi, u64 d) {
    asm("mov.b64 {%0, %1}, %2;" : "=f"(lo), "=f"(hi) : "l"(d));
}
// swap halves: (x, y) -> (y, x)
__device__ __forceinline__ u64 hswap(u64 a) {
    float lo, hi; unpk2(lo, hi, a);
    return pk2(hi, lo);
}
// round-to-nearest tf32 conversion
__device__ __forceinline__ u32 tf32c(float a) {
    u32 r; asm("cvt.rna.tf32.f32 %0, %1;" : "=r"(r) : "f"(a)); return r;
}

// ---------------------------------------------------------------------------
// GEMM-TC v4b: R13-proven kernel at SPLITK=8 + occupancy 2.
// CTA tile 128x128, BK=16, 256 threads = 8 warps (2m x 4n of 64x32 tiles).
// grid (4, 8, 8) = 256 CTAs; smem 34.8 KB, launch_bounds(256,2) -> 2 CTAs/SM
// = 4 warps/SMSP (2x latency hiding), all 256 resident in one wave.
// K/CTA = 256 -> 16 iters.  k-major smem, pad 136 (frag banks all-distinct).
// Loader-side cvt.rna tf32 (proven rel_err 5.7e-5).
// ---------------------------------------------------------------------------
__global__ __launch_bounds__(256, 2)
void gemm_tc4(const float* __restrict__ A, const float* __restrict__ Wm)
{
    __shared__ __align__(16) u32 As[2][16][136];
    __shared__ __align__(16) u32 Ws[2][16][136];

    const int t  = threadIdx.x;
    const int n0 = blockIdx.x * 128;
    const int m0 = blockIdx.y * 128;
    const int kb = blockIdx.z * 256;

    // loader mapping (coalesced float4 LDG; A and W symmetric, 128 rows each)
    const int r  = t >> 1;             // row 0..127
    const int kh = (t & 1) << 3;       // 0 or 8

    const float* Ap = A  + (size_t)(m0 + r) * 2048 + kb + kh;
    const float* Wp = Wm + (size_t)(n0 + r) * 2048 + kb + kh;

    // mma mapping
    const int lane = t & 31;
    const int wid  = t >> 5;
    const int wm   = wid >> 2;         // 0..1  (m half, 64 rows)
    const int wn   = wid & 3;          // 0..3  (n quarter, 32 cols)
    const int mr   = lane >> 2;        // 0..7
    const int kc   = lane & 3;         // 0..3

    float acc[4][4][4];
    #pragma unroll
    for (int mt = 0; mt < 4; ++mt)
        #pragma unroll
        for (int nt = 0; nt < 4; ++nt)
            #pragma unroll
            for (int i = 0; i < 4; ++i) acc[mt][nt][i] = 0.f;

    float4 pa0 = *(const float4*)Ap;
    float4 pa1 = *(const float4*)(Ap + 4);
    float4 pw0 = *(const float4*)Wp;
    float4 pw1 = *(const float4*)(Wp + 4);

    #pragma unroll 1
    for (int it = 0; it < 16; ++it) {
        const int buf = it & 1;
        As[buf][kh + 0][r] = tf32c(pa0.x); As[buf][kh + 1][r] = tf32c(pa0.y);
        As[buf][kh + 2][r] = tf32c(pa0.z); As[buf][kh + 3][r] = tf32c(pa0.w);
        As[buf][kh + 4][r] = tf32c(pa1.x); As[buf][kh + 5][r] = tf32c(pa1.y);
        As[buf][kh + 6][r] = tf32c(pa1.z); As[buf][kh + 7][r] = tf32c(pa1.w);
        Ws[buf][kh + 0][r] = tf32c(pw0.x); Ws[buf][kh + 1][r] = tf32c(pw0.y);
        Ws[buf][kh + 2][r] = tf32c(pw0.z); Ws[buf][kh + 3][r] = tf32c(pw0.w);
        Ws[buf][kh + 4][r] = tf32c(pw1.x); Ws[buf][kh + 5][r] = tf32c(pw1.y);
        Ws[buf][kh + 6][r] = tf32c(pw1.z); Ws[buf][kh + 7][r] = tf32c(pw1.w);

        if (it + 1 < 16) {
            const float* Ap2 = Ap + (it + 1) * 16;
            const float* Wp2 = Wp + (it + 1) * 16;
            pa0 = *(const float4*)Ap2; pa1 = *(const float4*)(Ap2 + 4);
            pw0 = *(const float4*)Wp2; pw1 = *(const float4*)(Wp2 + 4);
        }
        __syncthreads();

        #pragma unroll
        for (int ks = 0; ks < 16; ks += 8) {
            u32 af[4][4];
            #pragma unroll
            for (int mt = 0; mt < 4; ++mt) {
                int m = wm * 64 + mt * 16 + mr;
                af[mt][0] = As[buf][ks + kc][m];
                af[mt][1] = As[buf][ks + kc][m + 8];
                af[mt][2] = As[buf][ks + kc + 4][m];
                af[mt][3] = As[buf][ks + kc + 4][m + 8];
            }
            u32 bf[4][2];
            #pragma unroll
            for (int nt = 0; nt < 4; ++nt) {
                int n = wn * 32 + nt * 8 + mr;
                bf[nt][0] = Ws[buf][ks + kc][n];
                bf[nt][1] = Ws[buf][ks + kc + 4][n];
            }
            #pragma unroll
            for (int mt = 0; mt < 4; ++mt)
                #pragma unroll
                for (int nt = 0; nt < 4; ++nt) {
                    asm volatile(
                        "mma.sync.aligned.m16n8k8.row.col.f32.tf32.tf32.f32 "
                        "{%0,%1,%2,%3}, {%4,%5,%6,%7}, {%8,%9}, {%0,%1,%2,%3};"
                        : "+f"(acc[mt][nt][0]), "+f"(acc[mt][nt][1]),
                          "+f"(acc[mt][nt][2]), "+f"(acc[mt][nt][3])
                        : "r"(af[mt][0]), "r"(af[mt][1]),
                          "r"(af[mt][2]), "r"(af[mt][3]),
                          "r"(bf[nt][0]), "r"(bf[nt][1]));
                }
        }
        // no bottom sync: next iter's STS targets the other buffer.
    }

    float* Cp = g_com4[blockIdx.z];
    #pragma unroll
    for (int mt = 0; mt < 4; ++mt) {
        #pragma unroll
        for (int nt = 0; nt < 4; ++nt) {
            int row = m0 + wm * 64 + mt * 16 + mr;
            int col = n0 + wn * 32 + nt * 8 + 2 * kc;
            *(float2*)&Cp[(size_t)row * 512 + col] =
                make_float2(acc[mt][nt][0], acc[mt][nt][1]);
            *(float2*)&Cp[(size_t)(row + 8) * 512 + col] =
                make_float2(acc[mt][nt][2], acc[mt][nt][3]);
        }
    }
}

// ---------------------------------------------------------------------------
// Quantum circuit (R5-proven, ~51us, FROZEN): 1 CTA per batch row, state
// (4096 complex, AoS u64) in SMEM.  Wire w <-> bit (11 - w).
// Swizzle a(i) = i ^ ((i>>4) & 0xF).
// ---------------------------------------------------------------------------
__device__ __forceinline__ int swz(int i) { return i ^ ((i >> 4) & 0xF); }

// Packed complex 2x2 gate on pairs over local bit LB.
// c[8] splats: c[2e] = (m.x, m.x), c[2e+1] = (-m.y, m.y)  (negation folded).
template<int LB>
__device__ __forceinline__ void rot2(u64* v, const u64* __restrict__ cf)
{
    u64 c0 = cf[0], c1 = cf[1], c2 = cf[2], c3 = cf[3];
    u64 c4 = cf[4], c5 = cf[5], c6 = cf[6], c7 = cf[7];
    #pragma unroll
    for (int p = 0; p < 8; ++p) {
        int k0 = ((p >> LB) << (LB + 1)) | (p & ((1 << LB) - 1));
        int k1 = k0 | (1 << LB);
        u64 A = v[k0], B = v[k1];
        u64 As_ = hswap(A), Bs = hswap(B);
        v[k0] = fma2(c0, A, fma2(c1, As_, fma2(c2, B, mul2(c3, Bs))));
        v[k1] = fma2(c4, A, fma2(c5, As_, fma2(c6, B, mul2(c7, Bs))));
    }
}

// Unscaled Hadamard butterfly (scale folded into final reduction).
template<int LB>
__device__ __forceinline__ void h2(u64* v, u64 neg1)
{
    #pragma unroll
    for (int p = 0; p < 8; ++p) {
        int k0 = ((p >> LB) << (LB + 1)) | (p & ((1 << LB) - 1));
        int k1 = k0 | (1 << LB);
        u64 A = v[k0], B = v[k1];
        v[k0] = add2(A, B);
        v[k1] = fma2(neg1, B, A);
    }
}

// Net gather index of the 12-CNOT chain with range R (GF(2)-linear).
template<int R>
__device__ __forceinline__ int cnotG(int i)
{
    #pragma unroll
    for (int w = 11; w >= 0; --w) {
        int pc = 11 - w;
        int pt = 11 - ((w + R) % 12);
        i ^= ((i >> pc) & 1) << pt;
    }
    return i;
}

__global__ __launch_bounds__(256, 2)
void circuit_kernel(const float* __restrict__ x,    // (1024, 2048) img angles
                    const float* __restrict__ bias, // (512,)
                    const float* __restrict__ qp,   // (2, 12, 3)
                    float* __restrict__ out)        // (1024,)
{
    __shared__ u64 st[4096];             // 32 KB state (packed complex)
    __shared__ u64 cf2[2][12][8];        // splatted gate coefficients
    __shared__ float red[8];

    const int t = threadIdx.x;
    const int b = blockIdx.x;
    const float* img = x + (size_t)b * 2048;
    const size_t crow = (size_t)b * 512;

    // --- Rot matrices, splatted: Rot = RZ(omega) RY(theta) RZ(phi) ---
    if (t < 24) {
        int l = t / 12, w = t % 12;
        float phi = qp[(l * 12 + w) * 3 + 0];
        float th  = qp[(l * 12 + w) * 3 + 1];
        float om  = qp[(l * 12 + w) * 3 + 2];
        float sh, ch;  sincosf(0.5f * th, &sh, &ch);
        float sa, ca;  sincosf(0.5f * (phi + om), &sa, &ca);
        float sb, cb;  sincosf(0.5f * (phi - om), &sb, &cb);
        u64* c = cf2[l][w];
        c[0] = pk2( ch * ca,  ch * ca);
        c[1] = pk2( ch * sa, -ch * sa);
        c[2] = pk2(-sh * cb, -sh * cb);
        c[3] = pk2( sh * sb, -sh * sb);
        c[4] = pk2( sh * cb,  sh * cb);
        c[5] = pk2( sh * sb, -sh * sb);
        c[6] = pk2( ch * ca,  ch * ca);
        c[7] = pk2(-ch * sa,  ch * sa);
    }
    __syncthreads();

    const u64 neg1 = pk2(-1.f, -1.f);
    u64 v[16];

    // ===== Pass 1 (A: bits 0-3 local) : analytic FRQI(com), L0 Rots 11..8
    #pragma unroll
    for (int k = 0; k < 16; ++k) {
        int i = (t << 4) | k;
        if (i & 3) {
            v[k] = 0ull;
        } else {
            int j = (i >> 2) & 511;
            int aidx = __brev((unsigned)j) >> 23;
            float comv = bias[aidx];
            #pragma unroll
            for (int s = 0; s < SPLITK; ++s) comv += g_com4[s][crow + aidx];
            float sn, cs; __sincosf(0.5f * comv, &sn, &cs);
            float amp = ((i >> 11) & 1) ? sn : cs;
            v[k] = pk2(amp * 0.04419417382415922f, 0.f);  // 1/sqrt(512)
        }
    }
    rot2<0>(v, cf2[0][11]); rot2<1>(v, cf2[0][10]);
    rot2<2>(v, cf2[0][9]);  rot2<3>(v, cf2[0][8]);
    #pragma unroll
    for (int k = 0; k < 16; ++k) st[swz((t << 4) | k)] = v[k];
    __syncthreads();

    // ===== Pass 2 (B: bits 4-7) : L0 Rots 7..4
    #pragma unroll
    for (int k = 0; k < 16; ++k) v[k] = st[swz(((t >> 4) << 8) | (k << 4) | (t & 15))];
    rot2<0>(v, cf2[0][7]); rot2<1>(v, cf2[0][6]);
    rot2<2>(v, cf2[0][5]); rot2<3>(v, cf2[0][4]);
    #pragma unroll
    for (int k = 0; k < 16; ++k) st[swz(((t >> 4) << 8) | (k << 4) | (t & 15))] = v[k];
    __syncthreads();

    // ===== Pass 3 (C: bits 8-11) : L0 Rots 3..0
    #pragma unroll
    for (int k = 0; k < 16; ++k) v[k] = st[swz((k << 8) | t)];
    rot2<0>(v, cf2[0][3]); rot2<1>(v, cf2[0][2]);
    rot2<2>(v, cf2[0][1]); rot2<3>(v, cf2[0][0]);
    #pragma unroll
    for (int k = 0; k < 16; ++k) st[swz((k << 8) | t)] = v[k];
    __syncthreads();

    // ===== Pass 4 (A) : CNOT r=1 folded gather, L1 Rots 11..8
    {
        int base = cnotG<1>(t << 4);
        int m0 = cnotG<1>(1), m1 = cnotG<1>(2), m2 = cnotG<1>(4), m3 = cnotG<1>(8);
        #pragma unroll
        for (int k = 0; k < 16; ++k) {
            int gi = base ^ ((k & 1) ? m0 : 0) ^ ((k & 2) ? m1 : 0)
                          ^ ((k & 4) ? m2 : 0) ^ ((k & 8) ? m3 : 0);
            v[k] = st[swz(gi)];
        }
    }
    __syncthreads();
    rot2<0>(v, cf2[1][11]); rot2<1>(v, cf2[1][10]);
    rot2<2>(v, cf2[1][9]);  rot2<3>(v, cf2[1][8]);
    #pragma unroll
    for (int k = 0; k < 16; ++k) st[swz((t << 4) | k)] = v[k];
    __syncthreads();

    // ===== Pass 5 (B) : L1 Rots 7..4
    #pragma unroll
    for (int k = 0; k < 16; ++k) v[k] = st[swz(((t >> 4) << 8) | (k << 4) | (t & 15))];
    rot2<0>(v, cf2[1][7]); rot2<1>(v, cf2[1][6]);
    rot2<2>(v, cf2[1][5]); rot2<3>(v, cf2[1][4]);
    #pragma unroll
    for (int k = 0; k < 16; ++k) st[swz(((t >> 4) << 8) | (k << 4) | (t & 15))] = v[k];
    __syncthreads();

    // ===== Pass 6 (C) : L1 Rots 3..0
    #pragma unroll
    for (int k = 0; k < 16; ++k) v[k] = st[swz((k << 8) | t)];
    rot2<0>(v, cf2[1][3]); rot2<1>(v, cf2[1][2]);
    rot2<2>(v, cf2[1][1]); rot2<3>(v, cf2[1][0]);
    #pragma unroll
    for (int k = 0; k < 16; ++k) st[swz((k << 8) | t)] = v[k];
    __syncthreads();

    // ===== Pass 7 (A) : CNOT r=2 folded gather, H bits 0-3 (unscaled)
    {
        int base = cnotG<2>(t << 4);
        int m0 = cnotG<2>(1), m1 = cnotG<2>(2), m2 = cnotG<2>(4), m3 = cnotG<2>(8);
        #pragma unroll
        for (int k = 0; k < 16; ++k) {
            int gi = base ^ ((k & 1) ? m0 : 0) ^ ((k & 2) ? m1 : 0)
                          ^ ((k & 4) ? m2 : 0) ^ ((k & 8) ? m3 : 0);
            v[k] = st[swz(gi)];
        }
    }
    __syncthreads();
    h2<0>(v, neg1); h2<1>(v, neg1); h2<2>(v, neg1); h2<3>(v, neg1);
    #pragma unroll
    for (int k = 0; k < 16; ++k) st[swz((t << 4) | k)] = v[k];
    __syncthreads();

    // ===== Pass 8 (B) : H bits 4-7 (unscaled)
    #pragma unroll
    for (int k = 0; k < 16; ++k) v[k] = st[swz(((t >> 4) << 8) | (k << 4) | (t & 15))];
    h2<0>(v, neg1); h2<1>(v, neg1); h2<2>(v, neg1); h2<3>(v, neg1);
    #pragma unroll
    for (int k = 0; k < 16; ++k) st[swz(((t >> 4) << 8) | (k << 4) | (t & 15))] = v[k];
    __syncthreads();

    // ===== Pass 9 (C) : H bits 8-10 (unscaled), UC-RY(img) on wire 0, measure
    #pragma unroll
    for (int k = 0; k < 16; ++k) v[k] = st[swz((k << 8) | t)];
    h2<0>(v, neg1); h2<1>(v, neg1); h2<2>(v, neg1);

    #pragma unroll
    for (int k0 = 0; k0 < 8; ++k0) {
        int i0 = (k0 << 8) | t;
        int aidx = __brev((unsigned)i0) >> 21;
        float sn, cs; __sincosf(0.5f * img[aidx], &sn, &cs);
        u64 A = v[k0], B = v[k0 + 8];
        u64 cs2 = pk2(cs, cs), sn2 = pk2(sn, sn), sn2n = pk2(-sn, -sn);
        v[k0]     = fma2(cs2, A, mul2(sn2n, B));
        v[k0 + 8] = fma2(sn2, A, mul2(cs2, B));
    }

    u64 accN = 0ull, accP = 0ull;
    #pragma unroll
    for (int k = 0; k < 8; ++k)  accN = fma2(v[k], v[k], accN);
    #pragma unroll
    for (int k = 8; k < 16; ++k) accP = fma2(v[k], v[k], accP);
    float pl, ph, nl, nh;
    unpk2(pl, ph, accP); unpk2(nl, nh, accN);
    float acc = (pl + ph) - (nl + nh);

    #pragma unroll
    for (int o = 16; o; o >>= 1) acc += __shfl_xor_sync(0xffffffffu, acc, o);
    if ((t & 31) == 0) red[t >> 5] = acc;
    __syncthreads();
    if (t == 0) {
        float s = 0.f;
        #pragma unroll
        for (int w = 0; w < 8; ++w) s += red[w];
        out[b] = s * (1.0f / 2048.0f);   // fold (1/sqrt(2))^11 (squared) scale
    }
}

// ---------------------------------------------------------------------------
extern "C" void kernel_launch(void* const* d_in, const int* in_sizes, int n_in,
                              void* d_out, int out_size)
{
    const float* x  = (const float*)d_in[0];   // (1024, 2, 32, 32) -> (1024, 2048)
    const float* Wm = (const float*)d_in[1];   // (512, 2048)
    const float* bb = (const float*)d_in[2];   // (512,)
    const float* qp = (const float*)d_in[3];   // (2, 12, 3)
    float* out = (float*)d_out;                // (1024,)

    dim3 gemm_grid(512 / 128, 1024 / 128, SPLITK);   // (4, 8, 8) = 256 CTAs
    gemm_tc4<<<gemm_grid, 256>>>(x, Wm);
    circuit_kernel<<<1024, 256>>>(x, bb, qp, out);
}

// round 16
// speedup vs baseline: 1.1061x; 1.0786x over previous
#include <cuda_runtime.h>
#include <cuda_bf16.h>
#include <math.h>

typedef unsigned long long u64;
typedef unsigned int u32;

#define SPLITK 8

// Split-K partial sums of x @ W^T (bias added in circuit kernel). No allocs.
__device__ float g_com4[SPLITK][1024 * 512];

// ---------------------------------------------------------------------------
// Packed fp32x2 helpers (PTX-only)
// ---------------------------------------------------------------------------
__device__ __forceinline__ u64 pk2(float lo, float hi) {
    u64 d; asm("mov.b64 %0, {%1, %2};" : "=l"(d) : "f"(lo), "f"(hi)); return d;
}
__device__ __forceinline__ u64 fma2(u64 a, u64 b, u64 c) {
    u64 d; asm("fma.rn.f32x2 %0, %1, %2, %3;" : "=l"(d) : "l"(a), "l"(b), "l"(c)); return d;
}
__device__ __forceinline__ u64 mul2(u64 a, u64 b) {
    u64 d; asm("mul.rn.f32x2 %0, %1, %2;" : "=l"(d) : "l"(a), "l"(b)); return d;
}
__device__ __forceinline__ u64 add2(u64 a, u64 b) {
    u64 d; asm("add.rn.f32x2 %0, %1, %2;" : "=l"(d) : "l"(a), "l"(b)); return d;
}
__device__ __forceinline__ void unpk2(float& lo, float& hi, u64 d) {
    asm("mov.b64 {%0, %1}, %2;" : "=f"(lo), "=f"(hi) : "l"(d));
}
// swap halves: (x, y) -> (y, x)
__device__ __forceinline__ u64 hswap(u64 a) {
    float lo, hi; unpk2(lo, hi, a);
    return pk2(hi, lo);
}
// pack two f32 into bf16x2 (lo = first arg)
__device__ __forceinline__ u32 bf2(float lo, float hi) {
    u32 r; asm("cvt.rn.bf16x2.f32 %0, %1, %2;" : "=r"(r) : "f"(hi), "f"(lo)); return r;
}

// ---------------------------------------------------------------------------
// GEMM-BF16: split-K partials of x @ W^T via mma.sync m16n8k16 bf16.
// Same structure as the proven R13/R15 kernel; k dimension stored as bf16x2
// pairs (kp = k>>1, 8 kp-rows per BK=16 tile).  Per iter: 24 LDS.32 feed
// 16 k16-MMAs (tensor + LSU instruction count both halved vs tf32 k8).
// CTA tile 128x128, 256 threads = 8 warps (2m x 4n of 64x32 warp tiles).
// grid (4, 8, 8) = 256 CTAs, occ 2 -> single wave.  K/CTA = 256 -> 16 iters.
// Frag banks (8*kc + mr) mod 32 all-distinct -> conflict-free.
// ---------------------------------------------------------------------------
__global__ __launch_bounds__(256, 2)
void gemm_bf16(const float* __restrict__ A, const float* __restrict__ Wm)
{
    __shared__ __align__(16) u32 As[2][8][136];   // [buf][kp][row] bf16x2
    __shared__ __align__(16) u32 Ws[2][8][136];

    const int t  = threadIdx.x;
    const int n0 = blockIdx.x * 128;
    const int m0 = blockIdx.y * 128;
    const int kb = blockIdx.z * 256;

    // loader mapping (coalesced float4 LDG; A and W symmetric, 128 rows each)
    const int r   = t >> 1;            // row 0..127
    const int kh  = (t & 1) << 3;      // k offset 0 or 8
    const int kp0 = (t & 1) << 2;      // kp offset 0 or 4

    const float* Ap = A  + (size_t)(m0 + r) * 2048 + kb + kh;
    const float* Wp = Wm + (size_t)(n0 + r) * 2048 + kb + kh;

    // mma mapping
    const int lane = t & 31;
    const int wid  = t >> 5;
    const int wm   = wid >> 2;         // 0..1  (m half, 64 rows)
    const int wn   = wid & 3;          // 0..3  (n quarter, 32 cols)
    const int mr   = lane >> 2;        // 0..7
    const int kc   = lane & 3;         // 0..3

    float acc[4][4][4];
    #pragma unroll
    for (int mt = 0; mt < 4; ++mt)
        #pragma unroll
        for (int nt = 0; nt < 4; ++nt)
            #pragma unroll
            for (int i = 0; i < 4; ++i) acc[mt][nt][i] = 0.f;

    float4 pa0 = *(const float4*)Ap;
    float4 pa1 = *(const float4*)(Ap + 4);
    float4 pw0 = *(const float4*)Wp;
    float4 pw1 = *(const float4*)(Wp + 4);

    #pragma unroll 1
    for (int it = 0; it < 16; ++it) {
        const int buf = it & 1;
        As[buf][kp0 + 0][r] = bf2(pa0.x, pa0.y);
        As[buf][kp0 + 1][r] = bf2(pa0.z, pa0.w);
        As[buf][kp0 + 2][r] = bf2(pa1.x, pa1.y);
        As[buf][kp0 + 3][r] = bf2(pa1.z, pa1.w);
        Ws[buf][kp0 + 0][r] = bf2(pw0.x, pw0.y);
        Ws[buf][kp0 + 1][r] = bf2(pw0.z, pw0.w);
        Ws[buf][kp0 + 2][r] = bf2(pw1.x, pw1.y);
        Ws[buf][kp0 + 3][r] = bf2(pw1.z, pw1.w);

        if (it + 1 < 16) {
            const float* Ap2 = Ap + (it + 1) * 16;
            const float* Wp2 = Wp + (it + 1) * 16;
            pa0 = *(const float4*)Ap2; pa1 = *(const float4*)(Ap2 + 4);
            pw0 = *(const float4*)Wp2; pw1 = *(const float4*)(Wp2 + 4);
        }
        __syncthreads();

        u32 af[4][4];
        #pragma unroll
        for (int mt = 0; mt < 4; ++mt) {
            int m = wm * 64 + mt * 16 + mr;
            af[mt][0] = As[buf][kc][m];        // (row m,   k 2kc..2kc+1)
            af[mt][1] = As[buf][kc][m + 8];    // (row m+8, same k)
            af[mt][2] = As[buf][kc + 4][m];    // (row m,   k 2kc+8..2kc+9)
            af[mt][3] = As[buf][kc + 4][m + 8];
        }
        u32 bf[4][2];
        #pragma unroll
        for (int nt = 0; nt < 4; ++nt) {
            int n = wn * 32 + nt * 8 + mr;
            bf[nt][0] = Ws[buf][kc][n];        // (n, k 2kc..2kc+1)
            bf[nt][1] = Ws[buf][kc + 4][n];    // (n, k 2kc+8..2kc+9)
        }
        #pragma unroll
        for (int mt = 0; mt < 4; ++mt)
            #pragma unroll
            for (int nt = 0; nt < 4; ++nt) {
                asm volatile(
                    "mma.sync.aligned.m16n8k16.row.col.f32.bf16.bf16.f32 "
                    "{%0,%1,%2,%3}, {%4,%5,%6,%7}, {%8,%9}, {%0,%1,%2,%3};"
                    : "+f"(acc[mt][nt][0]), "+f"(acc[mt][nt][1]),
                      "+f"(acc[mt][nt][2]), "+f"(acc[mt][nt][3])
                    : "r"(af[mt][0]), "r"(af[mt][1]),
                      "r"(af[mt][2]), "r"(af[mt][3]),
                      "r"(bf[nt][0]), "r"(bf[nt][1]));
            }
        // no bottom sync: next iter's STS targets the other buffer.
    }

    float* Cp = g_com4[blockIdx.z];
    #pragma unroll
    for (int mt = 0; mt < 4; ++mt) {
        #pragma unroll
        for (int nt = 0; nt < 4; ++nt) {
            int row = m0 + wm * 64 + mt * 16 + mr;
            int col = n0 + wn * 32 + nt * 8 + 2 * kc;
            *(float2*)&Cp[(size_t)row * 512 + col] =
                make_float2(acc[mt][nt][0], acc[mt][nt][1]);
            *(float2*)&Cp[(size_t)(row + 8) * 512 + col] =
                make_float2(acc[mt][nt][2], acc[mt][nt][3]);
        }
    }
}

// ---------------------------------------------------------------------------
// Quantum circuit (R5-proven, ~51us, FROZEN): 1 CTA per batch row, state
// (4096 complex, AoS u64) in SMEM.  Wire w <-> bit (11 - w).
// Swizzle a(i) = i ^ ((i>>4) & 0xF).
// ---------------------------------------------------------------------------
__device__ __forceinline__ int swz(int i) { return i ^ ((i >> 4) & 0xF); }

// Packed complex 2x2 gate on pairs over local bit LB.
// c[8] splats: c[2e] = (m.x, m.x), c[2e+1] = (-m.y, m.y)  (negation folded).
template<int LB>
__device__ __forceinline__ void rot2(u64* v, const u64* __restrict__ cf)
{
    u64 c0 = cf[0], c1 = cf[1], c2 = cf[2], c3 = cf[3];
    u64 c4 = cf[4], c5 = cf[5], c6 = cf[6], c7 = cf[7];
    #pragma unroll
    for (int p = 0; p < 8; ++p) {
        int k0 = ((p >> LB) << (LB + 1)) | (p & ((1 << LB) - 1));
        int k1 = k0 | (1 << LB);
        u64 A = v[k0], B = v[k1];
        u64 As_ = hswap(A), Bs = hswap(B);
        v[k0] = fma2(c0, A, fma2(c1, As_, fma2(c2, B, mul2(c3, Bs))));
        v[k1] = fma2(c4, A, fma2(c5, As_, fma2(c6, B, mul2(c7, Bs))));
    }
}

// Unscaled Hadamard butterfly (scale folded into final reduction).
template<int LB>
__device__ __forceinline__ void h2(u64* v, u64 neg1)
{
    #pragma unroll
    for (int p = 0; p < 8; ++p) {
        int k0 = ((p >> LB) << (LB + 1)) | (p & ((1 << LB) - 1));
        int k1 = k0 | (1 << LB);
        u64 A = v[k0], B = v[k1];
        v[k0] = add2(A, B);
        v[k1] = fma2(neg1, B, A);
    }
}

// Net gather index of the 12-CNOT chain with range R (GF(2)-linear).
template<int R>
__device__ __forceinline__ int cnotG(int i)
{
    #pragma unroll
    for (int w = 11; w >= 0; --w) {
        int pc = 11 - w;
        int pt = 11 - ((w + R) % 12);
        i ^= ((i >> pc) & 1) << pt;
    }
    return i;
}

__global__ __launch_bounds__(256, 2)
void circuit_kernel(const float* __restrict__ x,    // (1024, 2048) img angles
                    const float* __restrict__ bias, // (512,)
                    const float* __restrict__ qp,   // (2, 12, 3)
                    float* __restrict__ out)        // (1024,)
{
    __shared__ u64 st[4096];             // 32 KB state (packed complex)
    __shared__ u64 cf2[2][12][8];        // splatted gate coefficients
    __shared__ float red[8];

    const int t = threadIdx.x;
    const int b = blockIdx.x;
    const float* img = x + (size_t)b * 2048;
    const size_t crow = (size_t)b * 512;

    // --- Rot matrices, splatted: Rot = RZ(omega) RY(theta) RZ(phi) ---
    if (t < 24) {
        int l = t / 12, w = t % 12;
        float phi = qp[(l * 12 + w) * 3 + 0];
        float th  = qp[(l * 12 + w) * 3 + 1];
        float om  = qp[(l * 12 + w) * 3 + 2];
        float sh, ch;  sincosf(0.5f * th, &sh, &ch);
        float sa, ca;  sincosf(0.5f * (phi + om), &sa, &ca);
        float sb, cb;  sincosf(0.5f * (phi - om), &sb, &cb);
        u64* c = cf2[l][w];
        c[0] = pk2( ch * ca,  ch * ca);
        c[1] = pk2( ch * sa, -ch * sa);
        c[2] = pk2(-sh * cb, -sh * cb);
        c[3] = pk2( sh * sb, -sh * sb);
        c[4] = pk2( sh * cb,  sh * cb);
        c[5] = pk2( sh * sb, -sh * sb);
        c[6] = pk2( ch * ca,  ch * ca);
        c[7] = pk2(-ch * sa,  ch * sa);
    }
    __syncthreads();

    const u64 neg1 = pk2(-1.f, -1.f);
    u64 v[16];

    // ===== Pass 1 (A: bits 0-3 local) : analytic FRQI(com), L0 Rots 11..8
    #pragma unroll
    for (int k = 0; k < 16; ++k) {
        int i = (t << 4) | k;
        if (i & 3) {
            v[k] = 0ull;
        } else {
            int j = (i >> 2) & 511;
            int aidx = __brev((unsigned)j) >> 23;
            float comv = bias[aidx];
            #pragma unroll
            for (int s = 0; s < SPLITK; ++s) comv += g_com4[s][crow + aidx];
            float sn, cs; __sincosf(0.5f * comv, &sn, &cs);
            float amp = ((i >> 11) & 1) ? sn : cs;
            v[k] = pk2(amp * 0.04419417382415922f, 0.f);  // 1/sqrt(512)
        }
    }
    rot2<0>(v, cf2[0][11]); rot2<1>(v, cf2[0][10]);
    rot2<2>(v, cf2[0][9]);  rot2<3>(v, cf2[0][8]);
    #pragma unroll
    for (int k = 0; k < 16; ++k) st[swz((t << 4) | k)] = v[k];
    __syncthreads();

    // ===== Pass 2 (B: bits 4-7) : L0 Rots 7..4
    #pragma unroll
    for (int k = 0; k < 16; ++k) v[k] = st[swz(((t >> 4) << 8) | (k << 4) | (t & 15))];
    rot2<0>(v, cf2[0][7]); rot2<1>(v, cf2[0][6]);
    rot2<2>(v, cf2[0][5]); rot2<3>(v, cf2[0][4]);
    #pragma unroll
    for (int k = 0; k < 16; ++k) st[swz(((t >> 4) << 8) | (k << 4) | (t & 15))] = v[k];
    __syncthreads();

    // ===== Pass 3 (C: bits 8-11) : L0 Rots 3..0
    #pragma unroll
    for (int k = 0; k < 16; ++k) v[k] = st[swz((k << 8) | t)];
    rot2<0>(v, cf2[0][3]); rot2<1>(v, cf2[0][2]);
    rot2<2>(v, cf2[0][1]); rot2<3>(v, cf2[0][0]);
    #pragma unroll
    for (int k = 0; k < 16; ++k) st[swz((k << 8) | t)] = v[k];
    __syncthreads();

    // ===== Pass 4 (A) : CNOT r=1 folded gather, L1 Rots 11..8
    {
        int base = cnotG<1>(t << 4);
        int m0 = cnotG<1>(1), m1 = cnotG<1>(2), m2 = cnotG<1>(4), m3 = cnotG<1>(8);
        #pragma unroll
        for (int k = 0; k < 16; ++k) {
            int gi = base ^ ((k & 1) ? m0 : 0) ^ ((k & 2) ? m1 : 0)
                          ^ ((k & 4) ? m2 : 0) ^ ((k & 8) ? m3 : 0);
            v[k] = st[swz(gi)];
        }
    }
    __syncthreads();
    rot2<0>(v, cf2[1][11]); rot2<1>(v, cf2[1][10]);
    rot2<2>(v, cf2[1][9]);  rot2<3>(v, cf2[1][8]);
    #pragma unroll
    for (int k = 0; k < 16; ++k) st[swz((t << 4) | k)] = v[k];
    __syncthreads();

    // ===== Pass 5 (B) : L1 Rots 7..4
    #pragma unroll
    for (int k = 0; k < 16; ++k) v[k] = st[swz(((t >> 4) << 8) | (k << 4) | (t & 15))];
    rot2<0>(v, cf2[1][7]); rot2<1>(v, cf2[1][6]);
    rot2<2>(v, cf2[1][5]); rot2<3>(v, cf2[1][4]);
    #pragma unroll
    for (int k = 0; k < 16; ++k) st[swz(((t >> 4) << 8) | (k << 4) | (t & 15))] = v[k];
    __syncthreads();

    // ===== Pass 6 (C) : L1 Rots 3..0
    #pragma unroll
    for (int k = 0; k < 16; ++k) v[k] = st[swz((k << 8) | t)];
    rot2<0>(v, cf2[1][3]); rot2<1>(v, cf2[1][2]);
    rot2<2>(v, cf2[1][1]); rot2<3>(v, cf2[1][0]);
    #pragma unroll
    for (int k = 0; k < 16; ++k) st[swz((k << 8) | t)] = v[k];
    __syncthreads();

    // ===== Pass 7 (A) : CNOT r=2 folded gather, H bits 0-3 (unscaled)
    {
        int base = cnotG<2>(t << 4);
        int m0 = cnotG<2>(1), m1 = cnotG<2>(2), m2 = cnotG<2>(4), m3 = cnotG<2>(8);
        #pragma unroll
        for (int k = 0; k < 16; ++k) {
            int gi = base ^ ((k & 1) ? m0 : 0) ^ ((k & 2) ? m1 : 0)
                          ^ ((k & 4) ? m2 : 0) ^ ((k & 8) ? m3 : 0);
            v[k] = st[swz(gi)];
        }
    }
    __syncthreads();
    h2<0>(v, neg1); h2<1>(v, neg1); h2<2>(v, neg1); h2<3>(v, neg1);
    #pragma unroll
    for (int k = 0; k < 16; ++k) st[swz((t << 4) | k)] = v[k];
    __syncthreads();

    // ===== Pass 8 (B) : H bits 4-7 (unscaled)
    #pragma unroll
    for (int k = 0; k < 16; ++k) v[k] = st[swz(((t >> 4) << 8) | (k << 4) | (t & 15))];
    h2<0>(v, neg1); h2<1>(v, neg1); h2<2>(v, neg1); h2<3>(v, neg1);
    #pragma unroll
    for (int k = 0; k < 16; ++k) st[swz(((t >> 4) << 8) | (k << 4) | (t & 15))] = v[k];
    __syncthreads();

    // ===== Pass 9 (C) : H bits 8-10 (unscaled), UC-RY(img) on wire 0, measure
    #pragma unroll
    for (int k = 0; k < 16; ++k) v[k] = st[swz((k << 8) | t)];
    h2<0>(v, neg1); h2<1>(v, neg1); h2<2>(v, neg1);

    #pragma unroll
    for (int k0 = 0; k0 < 8; ++k0) {
        int i0 = (k0 << 8) | t;
        int aidx = __brev((unsigned)i0) >> 21;
        float sn, cs; __sincosf(0.5f * img[aidx], &sn, &cs);
        u64 A = v[k0], B = v[k0 + 8];
        u64 cs2 = pk2(cs, cs), sn2 = pk2(sn, sn), sn2n = pk2(-sn, -sn);
        v[k0]     = fma2(cs2, A, mul2(sn2n, B));
        v[k0 + 8] = fma2(sn2, A, mul2(cs2, B));
    }

    u64 accN = 0ull, accP = 0ull;
    #pragma unroll
    for (int k = 0; k < 8; ++k)  accN = fma2(v[k], v[k], accN);
    #pragma unroll
    for (int k = 8; k < 16; ++k) accP = fma2(v[k], v[k], accP);
    float pl, ph, nl, nh;
    unpk2(pl, ph, accP); unpk2(nl, nh, accN);
    float acc = (pl + ph) - (nl + nh);

    #pragma unroll
    for (int o = 16; o; o >>= 1) acc += __shfl_xor_sync(0xffffffffu, acc, o);
    if ((t & 31) == 0) red[t >> 5] = acc;
    __syncthreads();
    if (t == 0) {
        float s = 0.f;
        #pragma unroll
        for (int w = 0; w < 8; ++w) s += red[w];
        out[b] = s * (1.0f / 2048.0f);   // fold (1/sqrt(2))^11 (squared) scale
    }
}

// ---------------------------------------------------------------------------
extern "C" void kernel_launch(void* const* d_in, const int* in_sizes, int n_in,
                              void* d_out, int out_size)
{
    const float* x  = (const float*)d_in[0];   // (1024, 2, 32, 32) -> (1024, 2048)
    const float* Wm = (const float*)d_in[1];   // (512, 2048)
    const float* bb = (const float*)d_in[2];   // (512,)
    const float* qp = (const float*)d_in[3];   // (2, 12, 3)
    float* out = (float*)d_out;                // (1024,)

    dim3 gemm_grid(512 / 128, 1024 / 128, SPLITK);   // (4, 8, 8) = 256 CTAs
    gemm_bf16<<<gemm_grid, 256>>>(x, Wm);
    circuit_kernel<<<1024, 256>>>(x, bb, qp, out);
}